// round 1
// baseline (speedup 1.0000x reference)
#include <cuda_runtime.h>
#include <cstdint>
#include <cstddef>

// Problem dims (fixed by this problem instance)
#define HD 1024     // hidden dim H
#define FD 3584     // ffn dim F
#define NE 8        // experts
#define RD 79       // low-rank dim R
#define TMAX 8192   // max tokens (B*S = 4*2048)
#define AMAX (TMAX*2)  // max assignments (top-2)

// ----------------------------------------------------------------------------
// Scratch (device globals — no allocations allowed)
// ----------------------------------------------------------------------------
__device__ __align__(16) float g_P1[(size_t)AMAX * RD];
__device__ __align__(16) float g_P3[(size_t)AMAX * RD];
__device__ __align__(16) float g_Q2[(size_t)AMAX * RD];
__device__ __align__(16) float g_gate[(size_t)AMAX * FD];  // becomes Hact after silu*up
__device__ __align__(16) float g_up[(size_t)AMAX * FD];

__device__ int   g_counts[NE];
__device__ int   g_offsets[NE + 1];
__device__ int   g_cursor[NE];
__device__ int   g_tok[AMAX];      // token id per assignment (bucketed by expert)
__device__ float g_w[AMAX];        // combine weight per assignment
__device__ int   g_sel[TMAX * 2];  // per-token top-2 expert ids
__device__ float g_wt[TMAX * 2];   // per-token top-2 normalized weights

// ----------------------------------------------------------------------------
// K0: zero output + routing counters
// ----------------------------------------------------------------------------
__global__ void zero_kernel(float* __restrict__ out, size_t n) {
    size_t i = (size_t)blockIdx.x * blockDim.x + threadIdx.x;
    size_t stride = (size_t)gridDim.x * blockDim.x;
    for (; i < n; i += stride) out[i] = 0.0f;
    if (blockIdx.x == 0 && threadIdx.x < NE) {
        g_counts[threadIdx.x] = 0;
        g_cursor[threadIdx.x] = 0;
    }
}

// ----------------------------------------------------------------------------
// K1: router — logits, softmax, top-2, counts. One block per token.
// ----------------------------------------------------------------------------
__global__ void router_kernel(const float* __restrict__ x,
                              const float* __restrict__ gw,
                              float* __restrict__ logits_out) {
    int t = blockIdx.x;
    __shared__ float xs[HD];
    __shared__ float lg[NE];
    int tid = threadIdx.x;  // 256
    for (int i = tid; i < HD; i += 256) xs[i] = x[(size_t)t * HD + i];
    __syncthreads();
    int w = tid >> 5, lane = tid & 31;
    if (w < NE) {
        const float* grow = gw + (size_t)w * HD;
        float s = 0.0f;
        for (int k = lane; k < HD; k += 32) s += xs[k] * grow[k];
        #pragma unroll
        for (int o = 16; o > 0; o >>= 1) s += __shfl_xor_sync(0xffffffffu, s, o);
        if (lane == 0) lg[w] = s;
    }
    __syncthreads();
    if (tid == 0) {
        float l[NE];
        float m = -1e30f;
        #pragma unroll
        for (int e = 0; e < NE; e++) {
            l[e] = lg[e];
            logits_out[(size_t)t * NE + e] = l[e];
            if (l[e] > m) m = l[e];
        }
        float p[NE];
        #pragma unroll
        for (int e = 0; e < NE; e++) p[e] = expf(l[e] - m);
        // top-2, ties -> lowest index (matches jax top_k)
        int i0 = 0;
        #pragma unroll
        for (int e = 1; e < NE; e++) if (p[e] > p[i0]) i0 = e;
        int i1 = (i0 == 0) ? 1 : 0;
        #pragma unroll
        for (int e = 0; e < NE; e++) {
            if (e == i0) continue;
            if (p[e] > p[i1]) i1 = e;
        }
        float p0 = p[i0], p1 = p[i1];
        float inv = 1.0f / (p0 + p1);
        g_sel[t * 2 + 0] = i0;  g_wt[t * 2 + 0] = p0 * inv;
        g_sel[t * 2 + 1] = i1;  g_wt[t * 2 + 1] = p1 * inv;
        atomicAdd(&g_counts[i0], 1);
        atomicAdd(&g_counts[i1], 1);
    }
}

// ----------------------------------------------------------------------------
// K2: exclusive scan of 8 counts (single thread — trivial)
// ----------------------------------------------------------------------------
__global__ void scan_kernel() {
    int off = 0;
    g_offsets[0] = 0;
    for (int e = 0; e < NE; e++) {
        off += g_counts[e];
        g_offsets[e + 1] = off;
        g_cursor[e] = g_offsets[e];
    }
}

// ----------------------------------------------------------------------------
// K3: scatter tokens into per-expert buckets
// ----------------------------------------------------------------------------
__global__ void scatter_kernel(int T) {
    int t = blockIdx.x * blockDim.x + threadIdx.x;
    if (t >= T) return;
    #pragma unroll
    for (int j = 0; j < 2; j++) {
        int e = g_sel[t * 2 + j];
        int slot = atomicAdd(&g_cursor[e], 1);
        g_tok[slot] = t;
        g_w[slot] = g_wt[t * 2 + j];
    }
}

// ----------------------------------------------------------------------------
// Generic MoE GEMM: C[m,n] = sum_{k<K1} A1(row_m)[k]*B1[n,k] + sum_{r<K2} A2[m,r]*B2[n,r]
//   A1 row = (GATHER ? x[tok[ga]] : buf[ga]), row stride = K1
//   B1: per-expert [Nvalid, K1], B2: per-expert [Nvalid, K2]
//   EPI 0: C[ga*ldc + n] = acc          (n < Nvalid)
//   EPI 1: atomicAdd(out[tok*HD + n], w[ga]*acc)
// ----------------------------------------------------------------------------
template <int BM, int BN, int BK, int TM, int TN, int K1, int K2, bool GATHER, int EPI>
__global__ void gemm_moe(const float* __restrict__ A1,
                         const float* __restrict__ A2,
                         const float* __restrict__ B1base, size_t bs1,
                         const float* __restrict__ B2base, size_t bs2,
                         float* __restrict__ C, int ldc, int Nvalid,
                         float* __restrict__ outp) {
    constexpr int KT = K1 + K2;
    constexpr int NKT = (KT + BK - 1) / BK;
    constexpr int NT = (BM / TM) * (BN / TN);  // threads per block (256)

    int e = blockIdx.z;
    int base = g_offsets[e];
    int cnt = g_offsets[e + 1] - base;
    int m0 = blockIdx.y * BM;
    if (m0 >= cnt) return;
    int n0 = blockIdx.x * BN;

    const float* B1 = B1base + (size_t)e * bs1;
    const float* B2 = (K2 > 0) ? (B2base + (size_t)e * bs2) : nullptr;

    __shared__ float As[BK][BM];
    __shared__ float Bs[BK][BN];

    const int tid = threadIdx.x;
    const int trow = tid / (BN / TN);
    const int tcol = tid % (BN / TN);

    float acc[TM][TN];
    #pragma unroll
    for (int i = 0; i < TM; i++)
        #pragma unroll
        for (int j = 0; j < TN; j++) acc[i][j] = 0.0f;

    for (int kt = 0; kt < NKT; kt++) {
        const int kbase = kt * BK;
        // ---- load A tile ----
        #pragma unroll
        for (int idx = tid; idx < BM * BK / 4; idx += NT) {
            int row = idx / (BK / 4);
            int kq = (idx % (BK / 4)) * 4;
            float4 v = make_float4(0.f, 0.f, 0.f, 0.f);
            int m = m0 + row;
            if (m < cnt) {
                int ga = base + m;
                const float* arow = GATHER ? (A1 + (size_t)g_tok[ga] * K1)
                                           : (A1 + (size_t)ga * K1);
                if (kbase + BK <= K1) {
                    v = *reinterpret_cast<const float4*>(arow + kbase + kq);
                } else {
                    float tv[4];
                    #pragma unroll
                    for (int j = 0; j < 4; j++) {
                        int kg = kbase + kq + j;
                        float t = 0.0f;
                        if (kg < K1) t = arow[kg];
                        else if (K2 > 0 && kg < KT) t = A2[(size_t)ga * K2 + (kg - K1)];
                        tv[j] = t;
                    }
                    v = make_float4(tv[0], tv[1], tv[2], tv[3]);
                }
            }
            As[kq + 0][row] = v.x;
            As[kq + 1][row] = v.y;
            As[kq + 2][row] = v.z;
            As[kq + 3][row] = v.w;
        }
        // ---- load B tile ----
        #pragma unroll
        for (int idx = tid; idx < BN * BK / 4; idx += NT) {
            int row = idx / (BK / 4);
            int kq = (idx % (BK / 4)) * 4;
            float4 v = make_float4(0.f, 0.f, 0.f, 0.f);
            int n = n0 + row;
            if (n < Nvalid) {
                const float* brow = B1 + (size_t)n * K1;
                if (kbase + BK <= K1) {
                    v = *reinterpret_cast<const float4*>(brow + kbase + kq);
                } else {
                    float tv[4];
                    #pragma unroll
                    for (int j = 0; j < 4; j++) {
                        int kg = kbase + kq + j;
                        float t = 0.0f;
                        if (kg < K1) t = brow[kg];
                        else if (K2 > 0 && kg < KT) t = B2[(size_t)n * K2 + (kg - K1)];
                        tv[j] = t;
                    }
                    v = make_float4(tv[0], tv[1], tv[2], tv[3]);
                }
            }
            Bs[kq + 0][row] = v.x;
            Bs[kq + 1][row] = v.y;
            Bs[kq + 2][row] = v.z;
            Bs[kq + 3][row] = v.w;
        }
        __syncthreads();
        // ---- compute ----
        #pragma unroll
        for (int kk = 0; kk < BK; kk++) {
            float a[TM], b[TN];
            #pragma unroll
            for (int i = 0; i < TM; i++) a[i] = As[kk][trow * TM + i];
            #pragma unroll
            for (int j = 0; j < TN; j++) b[j] = Bs[kk][tcol * TN + j];
            #pragma unroll
            for (int i = 0; i < TM; i++)
                #pragma unroll
                for (int j = 0; j < TN; j++) acc[i][j] += a[i] * b[j];
        }
        __syncthreads();
    }

    // ---- epilogue ----
    #pragma unroll
    for (int i = 0; i < TM; i++) {
        int m = m0 + trow * TM + i;
        if (m >= cnt) continue;
        int ga = base + m;
        if (EPI == 0) {
            float* crow = C + (size_t)ga * ldc;
            #pragma unroll
            for (int j = 0; j < TN; j++) {
                int n = n0 + tcol * TN + j;
                if (n < Nvalid) crow[n] = acc[i][j];
            }
        } else {
            int tok = g_tok[ga];
            float wgt = g_w[ga];
            float* orow = outp + (size_t)tok * HD;
            #pragma unroll
            for (int j = 0; j < TN; j++) {
                int n = n0 + tcol * TN + j;
                atomicAdd(&orow[n], wgt * acc[i][j]);
            }
        }
    }
}

// ----------------------------------------------------------------------------
// K7: Hact = silu(gate) * up, in-place into g_gate
// ----------------------------------------------------------------------------
__global__ void silu_mul_kernel(float* __restrict__ g, const float* __restrict__ u, size_t n) {
    size_t i = (size_t)blockIdx.x * blockDim.x + threadIdx.x;
    size_t stride = (size_t)gridDim.x * blockDim.x;
    for (; i < n; i += stride) {
        float gv = g[i];
        float s = 1.0f / (1.0f + expf(-gv));
        g[i] = gv * s * u[i];
    }
}

// ----------------------------------------------------------------------------
// kernel_launch
// Inputs (metadata order): hidden_states, gate_w, W1, W2, W3, U1, V1, U2, V2, U3, V3
// Output: [out (T*H floats)] then [router_logits (T*E floats)]
// ----------------------------------------------------------------------------
extern "C" void kernel_launch(void* const* d_in, const int* in_sizes, int n_in,
                              void* d_out, int out_size) {
    const float* x  = (const float*)d_in[0];
    const float* gw = (const float*)d_in[1];
    const float* W1 = (const float*)d_in[2];
    const float* W2 = (const float*)d_in[3];
    const float* W3 = (const float*)d_in[4];
    const float* U1 = (const float*)d_in[5];
    const float* V1 = (const float*)d_in[6];
    const float* U2 = (const float*)d_in[7];
    const float* V2 = (const float*)d_in[8];
    const float* U3 = (const float*)d_in[9];
    const float* V3 = (const float*)d_in[10];
    (void)n_in; (void)out_size;

    const int T = in_sizes[0] / HD;      // 8192
    const int A = T * 2;                 // assignments

    float* out    = (float*)d_out;             // [T, HD]
    float* logits = out + (size_t)T * HD;      // [T, NE]

    // K0: zero out + counters
    zero_kernel<<<2048, 256>>>(out, (size_t)T * HD);
    // K1: router
    router_kernel<<<T, 256>>>(x, gw, logits);
    // K2: scan
    scan_kernel<<<1, 1>>>();
    // K3: scatter
    scatter_kernel<<<(T + 255) / 256, 256>>>(T);

    const int mt128 = (T + 127) / 128;   // max m-tiles per expert (BM=128)
    const int mt64  = (T + 63) / 64;     // BM=64

    // K4: P1 = X @ V1^T, P3 = X @ V3^T   (per-expert, gathered rows; N=79)
    {
        dim3 grid(1, mt64, NE);
        gemm_moe<64, 80, 16, 4, 5, HD, 0, true, 0><<<grid, 256>>>(
            x, nullptr, V1, (size_t)RD * HD, nullptr, 0, g_P1, RD, RD, nullptr);
        gemm_moe<64, 80, 16, 4, 5, HD, 0, true, 0><<<grid, 256>>>(
            x, nullptr, V3, (size_t)RD * HD, nullptr, 0, g_P3, RD, RD, nullptr);
    }

    // K5: gate = [X|P1] @ [W1|U1]^T  -> g_gate   (M=A, N=F, K=1103)
    // K6: up   = [X|P3] @ [W3|U3]^T  -> g_up
    {
        dim3 grid(FD / 128, mt128, NE);
        gemm_moe<128, 128, 8, 8, 8, HD, RD, true, 0><<<grid, 256>>>(
            x, g_P1, W1, (size_t)FD * HD, U1, (size_t)FD * RD, g_gate, FD, FD, nullptr);
        gemm_moe<128, 128, 8, 8, 8, HD, RD, true, 0><<<grid, 256>>>(
            x, g_P3, W3, (size_t)FD * HD, U3, (size_t)FD * RD, g_up, FD, FD, nullptr);
    }

    // K7: Hact = silu(gate)*up, in-place into g_gate
    silu_mul_kernel<<<4096, 256>>>(g_gate, g_up, (size_t)A * FD);

    // K8: Q2 = Hact @ V2^T  (N=79, K=F)
    {
        dim3 grid(1, mt64, NE);
        gemm_moe<64, 80, 16, 4, 5, FD, 0, false, 0><<<grid, 256>>>(
            g_gate, nullptr, V2, (size_t)RD * FD, nullptr, 0, g_Q2, RD, RD, nullptr);
    }

    // K9: out += w * ([Hact|Q2] @ [W2|U2]^T)  (M=A, N=H, K=3663), atomic scatter
    {
        dim3 grid(HD / 128, mt128, NE);
        gemm_moe<128, 128, 8, 8, 8, FD, RD, false, 1><<<grid, 256>>>(
            g_gate, g_Q2, W2, (size_t)HD * FD, U2, (size_t)HD * RD, nullptr, HD, HD, out);
    }
}

// round 2
// speedup vs baseline: 1.6951x; 1.6951x over previous
#include <cuda_runtime.h>
#include <cstdint>
#include <cstddef>

// Problem dims (fixed by this problem instance)
#define HD 1024     // hidden dim H
#define FD 3584     // ffn dim F
#define NE 8        // experts
#define RD 79       // low-rank dim R
#define TMAX 8192   // max tokens (B*S = 4*2048)
#define AMAX (TMAX*2)  // max assignments (top-2)

// ----------------------------------------------------------------------------
// Scratch (device globals — no allocations allowed)
// ----------------------------------------------------------------------------
__device__ __align__(16) float g_P1[(size_t)AMAX * RD];
__device__ __align__(16) float g_P3[(size_t)AMAX * RD];
__device__ __align__(16) float g_Q2[(size_t)AMAX * RD];
__device__ __align__(16) float g_gate[(size_t)AMAX * FD];  // becomes Hact after silu*up
__device__ __align__(16) float g_up[(size_t)AMAX * FD];

__device__ int   g_counts[NE];
__device__ int   g_offsets[NE + 1];
__device__ int   g_cursor[NE];
__device__ int   g_tok[AMAX];      // token id per assignment (bucketed by expert)
__device__ float g_w[AMAX];        // combine weight per assignment
__device__ int   g_sel[TMAX * 2];  // per-token top-2 expert ids
__device__ float g_wt[TMAX * 2];   // per-token top-2 normalized weights

// ----------------------------------------------------------------------------
// tf32 helpers
// ----------------------------------------------------------------------------
__device__ __forceinline__ float cvt_tf32(float x) {
    uint32_t u;
    asm("cvt.rna.tf32.f32 %0, %1;" : "=r"(u) : "f"(x));
    return __uint_as_float(u);
}
__device__ __forceinline__ float4 cvt_tf32_4(float4 v) {
    v.x = cvt_tf32(v.x); v.y = cvt_tf32(v.y);
    v.z = cvt_tf32(v.z); v.w = cvt_tf32(v.w);
    return v;
}

// ----------------------------------------------------------------------------
// K0: zero output + routing counters
// ----------------------------------------------------------------------------
__global__ void zero_kernel(float* __restrict__ out, size_t n) {
    size_t i = (size_t)blockIdx.x * blockDim.x + threadIdx.x;
    size_t stride = (size_t)gridDim.x * blockDim.x;
    for (; i < n; i += stride) out[i] = 0.0f;
    if (blockIdx.x == 0 && threadIdx.x < NE) {
        g_counts[threadIdx.x] = 0;
        g_cursor[threadIdx.x] = 0;
    }
}

// ----------------------------------------------------------------------------
// K1: router — logits, softmax, top-2, counts. One block per token. (fp32 exact)
// ----------------------------------------------------------------------------
__global__ void router_kernel(const float* __restrict__ x,
                              const float* __restrict__ gw,
                              float* __restrict__ logits_out) {
    int t = blockIdx.x;
    __shared__ float xs[HD];
    __shared__ float lg[NE];
    int tid = threadIdx.x;  // 256
    for (int i = tid; i < HD; i += 256) xs[i] = x[(size_t)t * HD + i];
    __syncthreads();
    int w = tid >> 5, lane = tid & 31;
    if (w < NE) {
        const float* grow = gw + (size_t)w * HD;
        float s = 0.0f;
        for (int k = lane; k < HD; k += 32) s += xs[k] * grow[k];
        #pragma unroll
        for (int o = 16; o > 0; o >>= 1) s += __shfl_xor_sync(0xffffffffu, s, o);
        if (lane == 0) lg[w] = s;
    }
    __syncthreads();
    if (tid == 0) {
        float l[NE];
        float m = -1e30f;
        #pragma unroll
        for (int e = 0; e < NE; e++) {
            l[e] = lg[e];
            logits_out[(size_t)t * NE + e] = l[e];
            if (l[e] > m) m = l[e];
        }
        float p[NE];
        #pragma unroll
        for (int e = 0; e < NE; e++) p[e] = expf(l[e] - m);
        int i0 = 0;
        #pragma unroll
        for (int e = 1; e < NE; e++) if (p[e] > p[i0]) i0 = e;
        int i1 = (i0 == 0) ? 1 : 0;
        #pragma unroll
        for (int e = 0; e < NE; e++) {
            if (e == i0) continue;
            if (p[e] > p[i1]) i1 = e;
        }
        float p0 = p[i0], p1 = p[i1];
        float inv = 1.0f / (p0 + p1);
        g_sel[t * 2 + 0] = i0;  g_wt[t * 2 + 0] = p0 * inv;
        g_sel[t * 2 + 1] = i1;  g_wt[t * 2 + 1] = p1 * inv;
        atomicAdd(&g_counts[i0], 1);
        atomicAdd(&g_counts[i1], 1);
    }
}

// ----------------------------------------------------------------------------
// K2: exclusive scan of 8 counts
// ----------------------------------------------------------------------------
__global__ void scan_kernel() {
    int off = 0;
    g_offsets[0] = 0;
    for (int e = 0; e < NE; e++) {
        off += g_counts[e];
        g_offsets[e + 1] = off;
        g_cursor[e] = g_offsets[e];
    }
}

// ----------------------------------------------------------------------------
// K3: scatter tokens into per-expert buckets
// ----------------------------------------------------------------------------
__global__ void scatter_kernel(int T) {
    int t = blockIdx.x * blockDim.x + threadIdx.x;
    if (t >= T) return;
    #pragma unroll
    for (int j = 0; j < 2; j++) {
        int e = g_sel[t * 2 + j];
        int slot = atomicAdd(&g_cursor[e], 1);
        g_tok[slot] = t;
        g_w[slot] = g_wt[t * 2 + j];
    }
}

// ----------------------------------------------------------------------------
// TF32 tensor-core MoE GEMM.
//   C[m,n] = sum_{k<K1} A1(row_m)[k]*B1[n,k] + sum_{r<K2} A2[m,r]*B2[n,r]
//   A1 row = (GATHER ? x[tok[ga]] : buf[ga]); per-expert B1 [*,K1], B2 [*,K2].
//   EPI 0: C[ga*ldc + n] = acc
//   EPI 1: atomicAdd(out[tok*HD + n], w[ga]*acc)
// Tiles: BM x BN x 32, 256 threads = 8 warps as WARPS_M x WARPS_N.
// Smem: row-major [row][36] — conflict-free for float4 STS and all frag LDS.
// Register-staged pipeline: LDG(t+1) overlaps mma(t); single smem buffer.
// ----------------------------------------------------------------------------
template <int BM, int BN, int WARPS_M, int WARPS_N, int K1, int K2, bool GATHER, int EPI>
__global__ __launch_bounds__(256, 1)
void gemm_tf32(const float* __restrict__ A1,
               const float* __restrict__ A2,
               const float* __restrict__ B1base, size_t bs1,
               const float* __restrict__ B2base, size_t bs2,
               float* __restrict__ C, int ldc, int Nvalid,
               float* __restrict__ outp) {
    constexpr int BK = 32;
    constexpr int NTHR = 256;
    constexpr int KT = K1 + K2;
    constexpr int NKT = (KT + BK - 1) / BK;
    constexpr int WM = BM / WARPS_M;
    constexpr int WN = BN / WARPS_N;
    constexpr int MT = WM / 16;   // m16 frags per warp
    constexpr int NTL = WN / 8;   // n8 frags per warp
    constexpr int LDA = BK + 4;   // 36 words: conflict-free pad
    constexpr int LA = BM * (BK / 4) / NTHR;                  // float4/thread, A
    constexpr int LB = (BN * (BK / 4) + NTHR - 1) / NTHR;     // float4/thread, B
    static_assert(BM * (BK / 4) % NTHR == 0, "A tile must divide evenly");

    const int e = blockIdx.z;
    const int base = g_offsets[e];
    const int cnt = g_offsets[e + 1] - base;
    const int m0 = blockIdx.y * BM;
    if (m0 >= cnt) return;
    const int n0 = blockIdx.x * BN;

    const float* B1 = B1base + (size_t)e * bs1;
    const float* B2 = (K2 > 0) ? (B2base + (size_t)e * bs2) : nullptr;

    __shared__ float As[BM][LDA];
    __shared__ float Bs[BN][LDA];

    const int tid = threadIdx.x;
    const int lane = tid & 31;
    const int wid = tid >> 5;
    const int wm = wid % WARPS_M;
    const int wn = wid / WARPS_M;

    // ---- per-thread load metadata (fixed across k-tiles) ----
    const float* aptr[LA];
    const float* a2ptr[LA];
    int arow[LA], akq[LA];
    bool aok[LA];
    #pragma unroll
    for (int i = 0; i < LA; i++) {
        int idx = tid + i * NTHR;
        arow[i] = idx >> 3;          // BK/4 == 8 chunks per row
        akq[i] = (idx & 7) * 4;
        int m = m0 + arow[i];
        aok[i] = (m < cnt);
        int ga = base + (aok[i] ? m : 0);
        aptr[i] = GATHER ? (A1 + (size_t)g_tok[ga] * K1) : (A1 + (size_t)ga * K1);
        a2ptr[i] = (K2 > 0) ? (A2 + (size_t)ga * K2) : nullptr;
    }
    const float* bptr[LB];
    const float* b2ptr[LB];
    int brow[LB], bkq[LB];
    bool bok[LB], bin[LB];
    #pragma unroll
    for (int i = 0; i < LB; i++) {
        int idx = tid + i * NTHR;
        bin[i] = (idx < BN * 8);
        int r = bin[i] ? (idx >> 3) : 0;
        brow[i] = r;
        bkq[i] = (idx & 7) * 4;
        int n = n0 + r;
        bok[i] = bin[i] && (n < Nvalid);
        int nn = bok[i] ? n : 0;
        bptr[i] = B1 + (size_t)nn * K1;
        b2ptr[i] = (K2 > 0) ? (B2 + (size_t)nn * K2) : nullptr;
    }

    float4 ra[LA], rb[LB];
    auto load_tiles = [&](int kt) {
        const int kbase = kt * BK;
        const bool fast = (kbase + BK <= K1);
        #pragma unroll
        for (int i = 0; i < LA; i++) {
            float4 v = make_float4(0.f, 0.f, 0.f, 0.f);
            if (aok[i]) {
                int kg = kbase + akq[i];
                if (fast) {
                    v = *reinterpret_cast<const float4*>(aptr[i] + kg);
                } else {
                    float t[4];
                    #pragma unroll
                    for (int j = 0; j < 4; j++) {
                        int k = kg + j;
                        float xv = 0.f;
                        if (k < K1) xv = aptr[i][k];
                        else if (K2 > 0 && k < KT) xv = a2ptr[i][k - K1];
                        t[j] = xv;
                    }
                    v = make_float4(t[0], t[1], t[2], t[3]);
                }
            }
            ra[i] = v;
        }
        #pragma unroll
        for (int i = 0; i < LB; i++) {
            float4 v = make_float4(0.f, 0.f, 0.f, 0.f);
            if (bok[i]) {
                int kg = kbase + bkq[i];
                if (fast) {
                    v = *reinterpret_cast<const float4*>(bptr[i] + kg);
                } else {
                    float t[4];
                    #pragma unroll
                    for (int j = 0; j < 4; j++) {
                        int k = kg + j;
                        float xv = 0.f;
                        if (k < K1) xv = bptr[i][k];
                        else if (K2 > 0 && k < KT) xv = b2ptr[i][k - K1];
                        t[j] = xv;
                    }
                    v = make_float4(t[0], t[1], t[2], t[3]);
                }
            }
            rb[i] = v;
        }
    };
    auto store_tiles = [&]() {
        #pragma unroll
        for (int i = 0; i < LA; i++)
            *reinterpret_cast<float4*>(&As[arow[i]][akq[i]]) = cvt_tf32_4(ra[i]);
        #pragma unroll
        for (int i = 0; i < LB; i++)
            if (bin[i])
                *reinterpret_cast<float4*>(&Bs[brow[i]][bkq[i]]) = cvt_tf32_4(rb[i]);
    };

    float acc[MT][NTL][4];
    #pragma unroll
    for (int mt = 0; mt < MT; mt++)
        #pragma unroll
        for (int nt = 0; nt < NTL; nt++)
            #pragma unroll
            for (int j = 0; j < 4; j++) acc[mt][nt][j] = 0.f;

    load_tiles(0);
    store_tiles();
    __syncthreads();

    for (int kt = 0; kt < NKT; kt++) {
        if (kt + 1 < NKT) load_tiles(kt + 1);  // overlap with mma below
        #pragma unroll
        for (int ks = 0; ks < BK / 8; ks++) {
            const int k0 = ks * 8 + (lane & 3);
            uint32_t afr[MT][4];
            uint32_t bfr[NTL][2];
            #pragma unroll
            for (int mt = 0; mt < MT; mt++) {
                int m = wm * WM + mt * 16 + (lane >> 2);
                afr[mt][0] = __float_as_uint(As[m][k0]);
                afr[mt][1] = __float_as_uint(As[m + 8][k0]);
                afr[mt][2] = __float_as_uint(As[m][k0 + 4]);
                afr[mt][3] = __float_as_uint(As[m + 8][k0 + 4]);
            }
            #pragma unroll
            for (int nt = 0; nt < NTL; nt++) {
                int n = wn * WN + nt * 8 + (lane >> 2);
                bfr[nt][0] = __float_as_uint(Bs[n][k0]);
                bfr[nt][1] = __float_as_uint(Bs[n][k0 + 4]);
            }
            #pragma unroll
            for (int mt = 0; mt < MT; mt++)
                #pragma unroll
                for (int nt = 0; nt < NTL; nt++) {
                    asm volatile(
                        "mma.sync.aligned.m16n8k8.row.col.f32.tf32.tf32.f32 "
                        "{%0,%1,%2,%3}, {%4,%5,%6,%7}, {%8,%9}, {%0,%1,%2,%3};\n"
                        : "+f"(acc[mt][nt][0]), "+f"(acc[mt][nt][1]),
                          "+f"(acc[mt][nt][2]), "+f"(acc[mt][nt][3])
                        : "r"(afr[mt][0]), "r"(afr[mt][1]),
                          "r"(afr[mt][2]), "r"(afr[mt][3]),
                          "r"(bfr[nt][0]), "r"(bfr[nt][1]));
                }
        }
        if (kt + 1 < NKT) {
            __syncthreads();
            store_tiles();
            __syncthreads();
        }
    }

    // ---- epilogue ----
    #pragma unroll
    for (int mt = 0; mt < MT; mt++) {
        #pragma unroll
        for (int h = 0; h < 2; h++) {
            int ml = wm * WM + mt * 16 + (lane >> 2) + h * 8;
            int m = m0 + ml;
            if (m >= cnt) continue;
            int ga = base + m;
            if (EPI == 0) {
                float* crow = C + (size_t)ga * ldc;
                #pragma unroll
                for (int nt = 0; nt < NTL; nt++) {
                    #pragma unroll
                    for (int j = 0; j < 2; j++) {
                        int n = n0 + wn * WN + nt * 8 + 2 * (lane & 3) + j;
                        if (n < Nvalid) crow[n] = acc[mt][nt][h * 2 + j];
                    }
                }
            } else {
                int tok = g_tok[ga];
                float wgt = g_w[ga];
                float* orow = outp + (size_t)tok * HD;
                #pragma unroll
                for (int nt = 0; nt < NTL; nt++) {
                    #pragma unroll
                    for (int j = 0; j < 2; j++) {
                        int n = n0 + wn * WN + nt * 8 + 2 * (lane & 3) + j;
                        if (n < Nvalid) atomicAdd(&orow[n], wgt * acc[mt][nt][h * 2 + j]);
                    }
                }
            }
        }
    }
}

// ----------------------------------------------------------------------------
// K7: Hact = silu(gate) * up, in-place into g_gate
// ----------------------------------------------------------------------------
__global__ void silu_mul_kernel(float* __restrict__ g, const float* __restrict__ u, size_t n) {
    size_t i = (size_t)blockIdx.x * blockDim.x + threadIdx.x;
    size_t stride = (size_t)gridDim.x * blockDim.x;
    for (; i < n; i += stride) {
        float gv = g[i];
        float s = 1.0f / (1.0f + expf(-gv));
        g[i] = gv * s * u[i];
    }
}

// ----------------------------------------------------------------------------
// kernel_launch
// Inputs: hidden_states, gate_w, W1, W2, W3, U1, V1, U2, V2, U3, V3
// Output: [out (T*H floats)] then [router_logits (T*E floats)]
// ----------------------------------------------------------------------------
extern "C" void kernel_launch(void* const* d_in, const int* in_sizes, int n_in,
                              void* d_out, int out_size) {
    const float* x  = (const float*)d_in[0];
    const float* gw = (const float*)d_in[1];
    const float* W1 = (const float*)d_in[2];
    const float* W2 = (const float*)d_in[3];
    const float* W3 = (const float*)d_in[4];
    const float* U1 = (const float*)d_in[5];
    const float* V1 = (const float*)d_in[6];
    const float* U2 = (const float*)d_in[7];
    const float* V2 = (const float*)d_in[8];
    const float* U3 = (const float*)d_in[9];
    const float* V3 = (const float*)d_in[10];
    (void)n_in; (void)out_size;

    const int T = in_sizes[0] / HD;      // 8192
    const int A = T * 2;                 // assignments

    float* out    = (float*)d_out;             // [T, HD]
    float* logits = out + (size_t)T * HD;      // [T, NE]

    zero_kernel<<<2048, 256>>>(out, (size_t)T * HD);
    router_kernel<<<T, 256>>>(x, gw, logits);
    scan_kernel<<<1, 1>>>();
    scatter_kernel<<<(T + 255) / 256, 256>>>(T);

    const int mt128 = (T + 127) / 128;   // 64 m-tiles per expert upper bound

    // K4: P1 = X @ V1^T, P3 = X @ V3^T   (per-expert, gathered rows; N=79)
    {
        dim3 grid(1, mt128, NE);
        gemm_tf32<128, 80, 8, 1, HD, 0, true, 0><<<grid, 256>>>(
            x, nullptr, V1, (size_t)RD * HD, nullptr, 0, g_P1, RD, RD, nullptr);
        gemm_tf32<128, 80, 8, 1, HD, 0, true, 0><<<grid, 256>>>(
            x, nullptr, V3, (size_t)RD * HD, nullptr, 0, g_P3, RD, RD, nullptr);
    }

    // K5/K6: gate = [X|P1]@[W1|U1]^T, up = [X|P3]@[W3|U3]^T   (M=A, N=F, K=1103)
    {
        dim3 grid(FD / 128, mt128, NE);
        gemm_tf32<128, 128, 2, 4, HD, RD, true, 0><<<grid, 256>>>(
            x, g_P1, W1, (size_t)FD * HD, U1, (size_t)FD * RD, g_gate, FD, FD, nullptr);
        gemm_tf32<128, 128, 2, 4, HD, RD, true, 0><<<grid, 256>>>(
            x, g_P3, W3, (size_t)FD * HD, U3, (size_t)FD * RD, g_up, FD, FD, nullptr);
    }

    // K7: Hact = silu(gate)*up
    silu_mul_kernel<<<4096, 256>>>(g_gate, g_up, (size_t)A * FD);

    // K8: Q2 = Hact @ V2^T  (N=79, K=F)
    {
        dim3 grid(1, mt128, NE);
        gemm_tf32<128, 80, 8, 1, FD, 0, false, 0><<<grid, 256>>>(
            g_gate, nullptr, V2, (size_t)RD * FD, nullptr, 0, g_Q2, RD, RD, nullptr);
    }

    // K9: out += w * ([Hact|Q2] @ [W2|U2]^T)  (M=A, N=H, K=3663), atomic scatter
    {
        dim3 grid(HD / 128, mt128, NE);
        gemm_tf32<128, 128, 2, 4, FD, RD, false, 1><<<grid, 256>>>(
            g_gate, g_Q2, W2, (size_t)HD * FD, U2, (size_t)HD * RD, nullptr, HD, HD, out);
    }
}